// round 1
// baseline (speedup 1.0000x reference)
#include <cuda_runtime.h>

// Problem constants: x (8, 2048, 256) fp32; output (8, 2048) fp32.
#define BB 8
#define NN 2048
#define HH 256

// Scratch (device globals; no allocation allowed).
// g_q / g_k stored TRANSPOSED per batch: [b][h][n] so attention smem staging is a
// straight copy (no transpose in the hot loop). g_q is pre-scaled by 1/sqrt(H).
__device__ float g_q[BB * HH * NN];
__device__ float g_k[BB * HH * NN];
__device__ float g_w[BB * NN];
__device__ float g_u[HH];
__device__ float g_c;

// ---------------- packed f32x2 helpers (Blackwell) ----------------
__device__ __forceinline__ unsigned long long ffma2(unsigned long long a,
                                                    unsigned long long b,
                                                    unsigned long long c) {
    unsigned long long d;
    asm("fma.rn.f32x2 %0, %1, %2, %3;" : "=l"(d) : "l"(a), "l"(b), "l"(c));
    return d;
}
__device__ __forceinline__ unsigned long long dup2(float x) {
    unsigned long long r;
    asm("mov.b64 %0, {%1, %1};" : "=l"(r) : "f"(x));
    return r;
}
__device__ __forceinline__ float2 unpk(unsigned long long v) {
    float2 r;
    asm("mov.b64 {%0, %1}, %2;" : "=f"(r.x), "=f"(r.y) : "l"(v));
    return r;
}
__device__ __forceinline__ void cp16(unsigned dst, const void* src) {
    asm volatile("cp.async.cg.shared.global [%0], [%1], 16;" :: "r"(dst), "l"(src));
}
__device__ __forceinline__ void cp_commit() {
    asm volatile("cp.async.commit_group;");
}
template <int N>
__device__ __forceinline__ void cp_wait() {
    asm volatile("cp.async.wait_group %0;" :: "n"(N) : "memory");
}

// ---------------- kernel 0: u = Wv @ Ww, c = bv . Ww ----------------
__global__ void prep_kernel(const float* __restrict__ Wv,
                            const float* __restrict__ Ww,
                            const float* __restrict__ bv) {
    int warp = threadIdx.x >> 5, lane = threadIdx.x & 31;
    for (int row = warp; row < HH; row += 8) {
        float s = 0.f;
        #pragma unroll
        for (int m = 0; m < 8; m++) s += Wv[row * HH + m * 32 + lane] * Ww[m * 32 + lane];
        for (int o = 16; o; o >>= 1) s += __shfl_down_sync(0xffffffffu, s, o);
        if (!lane) g_u[row] = s;
    }
    if (threadIdx.x == 0) {
        float c = 0.f;
        for (int j = 0; j < HH; j++) c += bv[j] * Ww[j];
        g_c = c;
    }
}

// ---------------- kernel 1: w[row] = x[row] . u + c ----------------
__global__ void w_kernel(const float* __restrict__ x) {
    int warp = threadIdx.x >> 5, lane = threadIdx.x & 31;
    int row = blockIdx.x * 8 + warp;
    const float* xr = x + (size_t)row * HH;
    float s = 0.f;
    #pragma unroll
    for (int m = 0; m < 8; m++) s += xr[m * 32 + lane] * g_u[m * 32 + lane];
    for (int o = 16; o; o >>= 1) s += __shfl_down_sync(0xffffffffu, s, o);
    if (!lane) g_w[row] = s + g_c;
}

// ---------------- kernel 2: Q/K GEMM (fp32, f32x2 packed FFMA) ----------------
// grid (128, 4): x tiles of 128 rows; y in {0,1}=q halves, {2,3}=k halves.
// Output written transposed [b][h][n]; q pre-scaled by 1/16.
__global__ __launch_bounds__(256, 1) void qk_kernel(
    const float* __restrict__ x, const float* __restrict__ Wq,
    const float* __restrict__ bq, const float* __restrict__ Wk,
    const float* __restrict__ bk) {
    __shared__ float xs[32 * 132];   // transposed x slice: xs[d][n]
    __shared__ float wsm[32 * 132];  // weight slice:      wsm[d][h]

    const int tid = threadIdx.x;
    const int hi = blockIdx.y;
    const float* W = (hi < 2) ? Wq : Wk;
    const float* bias = (hi < 2) ? bq : bk;
    float* outp = (hi < 2) ? g_q : g_k;
    const int h0 = (hi & 1) * 128;
    const float scale = (hi < 2) ? 0.0625f : 1.0f;
    const int n0 = blockIdx.x * 128;

    const int row0 = (tid >> 4) << 3;  // n micro-offset
    const int col0 = (tid & 15) << 3;  // h micro-offset

    unsigned long long acc[4][8];
    #pragma unroll
    for (int r = 0; r < 4; r++)
        #pragma unroll
        for (int c = 0; c < 8; c++) acc[r][c] = 0ULL;

    for (int kk = 0; kk < 8; kk++) {
        if (kk) __syncthreads();
        // stage x slice transposed
        #pragma unroll
        for (int i = 0; i < 4; i++) {
            int idx = tid + i * 256;
            int row = idx >> 3, f4 = idx & 7;
            float4 v = *(const float4*)(x + (size_t)(n0 + row) * HH + kk * 32 + f4 * 4);
            xs[(f4 * 4 + 0) * 132 + row] = v.x;
            xs[(f4 * 4 + 1) * 132 + row] = v.y;
            xs[(f4 * 4 + 2) * 132 + row] = v.z;
            xs[(f4 * 4 + 3) * 132 + row] = v.w;
        }
        // stage weight slice (already [d][h])
        #pragma unroll
        for (int i = 0; i < 4; i++) {
            int idx = tid + i * 256;
            int t = idx >> 5, c4 = idx & 31;
            *(float4*)(wsm + t * 132 + c4 * 4) =
                *(const float4*)(W + (size_t)(kk * 32 + t) * HH + h0 + c4 * 4);
        }
        __syncthreads();
        #pragma unroll 8
        for (int t = 0; t < 32; t++) {
            ulonglong2 A0 = *(const ulonglong2*)(xs + t * 132 + row0);
            ulonglong2 A1 = *(const ulonglong2*)(xs + t * 132 + row0 + 4);
            unsigned long long ap[4] = {A0.x, A0.y, A1.x, A1.y};
            const float* bp = wsm + t * 132 + col0;
            float4 b0 = *(const float4*)bp;
            float4 b1 = *(const float4*)(bp + 4);
            float bb[8] = {b0.x, b0.y, b0.z, b0.w, b1.x, b1.y, b1.z, b1.w};
            #pragma unroll
            for (int c = 0; c < 8; c++) {
                unsigned long long Bd = dup2(bb[c]);
                #pragma unroll
                for (int r = 0; r < 4; r++) acc[r][c] = ffma2(ap[r], Bd, acc[r][c]);
            }
        }
    }

    const int b = n0 >> 11;
    const int nloc = (n0 & 2047) + row0;
    #pragma unroll
    for (int c = 0; c < 8; c++) {
        int h = h0 + col0 + c;
        float bsv = bias[h];
        float2 p0 = unpk(acc[0][c]), p1 = unpk(acc[1][c]);
        float2 p2 = unpk(acc[2][c]), p3 = unpk(acc[3][c]);
        float4 lo = make_float4((p0.x + bsv) * scale, (p0.y + bsv) * scale,
                                (p1.x + bsv) * scale, (p1.y + bsv) * scale);
        float4 hv = make_float4((p2.x + bsv) * scale, (p2.y + bsv) * scale,
                                (p3.x + bsv) * scale, (p3.y + bsv) * scale);
        float* o = outp + ((size_t)(b * HH + h)) * NN + nloc;
        *(float4*)o = lo;
        *(float4*)(o + 4) = hv;
    }
}

// ---------------- kernel 3: fused attention ----------------
// grid (16, 8): q-tile of 128 rows per CTA, per batch. Streams all 2048 keys
// in 128-wide tiles; scores via f32x2 FFMA; softmax-weighted scalar reduction.
#define QS_F (256 * 132)
#define KSL_F (32 * 132)
#define SMEM_F (QS_F + 2 * KSL_F + 128 + 256)

__global__ __launch_bounds__(256, 1) void attn_kernel(const float* __restrict__ bw,
                                                      float* __restrict__ out) {
    extern __shared__ float sm[];
    float* qs = sm;                       // qs[h][n] full q tile (256 x 128)
    float* ks = sm + QS_F;                // double-buffered k slice (32 x 128)
    float* ws = sm + QS_F + 2 * KSL_F;    // key scalars w[m] for this tile
    float* snum = ws + 128;
    float* sden = snum + 128;

    const int tid = threadIdx.x;
    const int b = blockIdx.y;
    const int n0 = blockIdx.x * 128;
    const int row0 = (tid >> 4) << 3;  // q-row micro-offset
    const int col0 = (tid & 15) << 3;  // key micro-offset

    const unsigned qs_u = (unsigned)__cvta_generic_to_shared(qs);
    const unsigned ks_u = (unsigned)__cvta_generic_to_shared(ks);

    // async-stage the whole q tile (group 0)
    {
        const float* qsrc = g_q + (size_t)b * HH * NN + n0;
        #pragma unroll
        for (int i = 0; i < 32; i++) {
            int idx = tid + i * 256;
            int t = idx >> 5, ch = idx & 31;
            cp16(qs_u + (unsigned)(t * 132 + ch * 4) * 4, qsrc + (size_t)t * NN + ch * 4);
        }
        cp_commit();
    }

    float num[8], den[8];
    #pragma unroll
    for (int i = 0; i < 8; i++) { num[i] = 0.f; den[i] = 0.f; }

    const float* kbase = g_k + (size_t)b * HH * NN;

    for (int j = 0; j < 16; j++) {
        const int m0 = j * 128;
        if (j) __syncthreads();  // previous epilogue done (ws / buffers safe)
        if (tid < 128) ws[tid] = g_w[b * NN + m0 + tid];
        // slice 0 of this tile -> buf0
        #pragma unroll
        for (int i = 0; i < 4; i++) {
            int idx = tid + i * 256;
            int tl = idx >> 5, ch = idx & 31;
            cp16(ks_u + (unsigned)(tl * 132 + ch * 4) * 4,
                 kbase + (size_t)tl * NN + m0 + ch * 4);
        }
        cp_commit();

        unsigned long long sacc[4][8];
        #pragma unroll
        for (int r = 0; r < 4; r++)
            #pragma unroll
            for (int c = 0; c < 8; c++) sacc[r][c] = 0ULL;

        for (int s = 0; s < 8; s++) {
            if (s < 7) {  // prefetch next slice into the other buffer
                int nb = (s + 1) & 1;
                #pragma unroll
                for (int i = 0; i < 4; i++) {
                    int idx = tid + i * 256;
                    int tl = idx >> 5, ch = idx & 31;
                    cp16(ks_u + (unsigned)(nb * KSL_F + tl * 132 + ch * 4) * 4,
                         kbase + (size_t)((s + 1) * 32 + tl) * NN + m0 + ch * 4);
                }
                cp_commit();
                cp_wait<1>();
            } else {
                cp_wait<0>();
            }
            __syncthreads();
            const float* qb = qs + (s * 32) * 132;
            const float* kb = ks + (s & 1) * KSL_F;
            #pragma unroll 8
            for (int t = 0; t < 32; t++) {
                ulonglong2 A0 = *(const ulonglong2*)(qb + t * 132 + row0);
                ulonglong2 A1 = *(const ulonglong2*)(qb + t * 132 + row0 + 4);
                unsigned long long ap[4] = {A0.x, A0.y, A1.x, A1.y};
                const float* bp = kb + t * 132 + col0;
                float4 b0 = *(const float4*)bp;
                float4 b1 = *(const float4*)(bp + 4);
                float bb[8] = {b0.x, b0.y, b0.z, b0.w, b1.x, b1.y, b1.z, b1.w};
                #pragma unroll
                for (int c = 0; c < 8; c++) {
                    unsigned long long Bd = dup2(bb[c]);
                    #pragma unroll
                    for (int r = 0; r < 4; r++) sacc[r][c] = ffma2(ap[r], Bd, sacc[r][c]);
                }
            }
            __syncthreads();  // all threads done before this buffer is refilled
        }

        // epilogue: exp + weighted accumulation (scores already include 1/sqrt(H))
        #pragma unroll
        for (int c = 0; c < 8; c++) {
            float wv = ws[col0 + c];
            #pragma unroll
            for (int r = 0; r < 4; r++) {
                float2 p = unpk(sacc[r][c]);
                float e0 = __expf(p.x), e1 = __expf(p.y);
                num[2 * r] += e0 * wv;     den[2 * r] += e0;
                num[2 * r + 1] += e1 * wv; den[2 * r + 1] += e1;
            }
        }
    }

    // cross-thread reduction over the 16 column-groups
    __syncthreads();
    if (tid < 128) { snum[tid] = 0.f; sden[tid] = 0.f; }
    __syncthreads();
    #pragma unroll
    for (int i = 0; i < 8; i++) {
        atomicAdd(&snum[row0 + i], num[i]);
        atomicAdd(&sden[row0 + i], den[i]);
    }
    __syncthreads();
    if (tid < 128) {
        out[b * NN + n0 + tid] = snum[tid] / sden[tid] + bw[0];
    }
}

// ---------------- launch ----------------
extern "C" void kernel_launch(void* const* d_in, const int* in_sizes, int n_in,
                              void* d_out, int out_size) {
    const float* x  = (const float*)d_in[0];
    const float* Wq = (const float*)d_in[1];
    const float* bq = (const float*)d_in[2];
    const float* Wk = (const float*)d_in[3];
    const float* bk = (const float*)d_in[4];
    const float* Wv = (const float*)d_in[5];
    const float* bv = (const float*)d_in[6];
    const float* Ww = (const float*)d_in[7];
    const float* bw = (const float*)d_in[8];
    float* out = (float*)d_out;

    cudaFuncSetAttribute(attn_kernel, cudaFuncAttributeMaxDynamicSharedMemorySize,
                         SMEM_F * 4);

    prep_kernel<<<1, 256>>>(Wv, Ww, bv);
    w_kernel<<<BB * NN / 8, 256>>>(x);
    qk_kernel<<<dim3(128, 4), 256>>>(x, Wq, bq, Wk, bk);
    attn_kernel<<<dim3(16, 8), 256, SMEM_F * 4>>>(bw, out);
}

// round 2
// speedup vs baseline: 1.0031x; 1.0031x over previous
#include <cuda_runtime.h>

// Problem constants: x (8, 2048, 256) fp32; output (8, 2048) fp32.
#define BB 8
#define NN 2048
#define HH 256

// Scratch (device globals; no allocation allowed).
// g_q / g_k stored TRANSPOSED per batch: [b][h][n] so attention smem staging is a
// straight copy (no transpose in the hot loop). g_q is pre-scaled by 1/sqrt(H).
__device__ float g_q[BB * HH * NN];
__device__ float g_k[BB * HH * NN];
__device__ float g_w[BB * NN];
__device__ float g_u[HH];
__device__ float g_c;

// ---------------- packed f32x2 helpers (Blackwell) ----------------
__device__ __forceinline__ unsigned long long ffma2(unsigned long long a,
                                                    unsigned long long b,
                                                    unsigned long long c) {
    unsigned long long d;
    asm("fma.rn.f32x2 %0, %1, %2, %3;" : "=l"(d) : "l"(a), "l"(b), "l"(c));
    return d;
}
__device__ __forceinline__ unsigned long long dup2(float x) {
    unsigned long long r;
    asm("mov.b64 %0, {%1, %1};" : "=l"(r) : "f"(x));
    return r;
}
__device__ __forceinline__ float2 unpk(unsigned long long v) {
    float2 r;
    asm("mov.b64 {%0, %1}, %2;" : "=f"(r.x), "=f"(r.y) : "l"(v));
    return r;
}
__device__ __forceinline__ void cp16(unsigned dst, const void* src) {
    asm volatile("cp.async.cg.shared.global [%0], [%1], 16;" :: "r"(dst), "l"(src));
}
__device__ __forceinline__ void cp_commit() {
    asm volatile("cp.async.commit_group;");
}
template <int N>
__device__ __forceinline__ void cp_wait() {
    asm volatile("cp.async.wait_group %0;" :: "n"(N) : "memory");
}

// ---------------- kernel 0: u = Wv @ Ww, c = bv . Ww ----------------
__global__ void prep_kernel(const float* __restrict__ Wv,
                            const float* __restrict__ Ww,
                            const float* __restrict__ bv) {
    int warp = threadIdx.x >> 5, lane = threadIdx.x & 31;
    for (int row = warp; row < HH; row += 8) {
        float s = 0.f;
        #pragma unroll
        for (int m = 0; m < 8; m++) s += Wv[row * HH + m * 32 + lane] * Ww[m * 32 + lane];
        for (int o = 16; o; o >>= 1) s += __shfl_down_sync(0xffffffffu, s, o);
        if (!lane) g_u[row] = s;
    }
    if (threadIdx.x == 0) {
        float c = 0.f;
        for (int j = 0; j < HH; j++) c += bv[j] * Ww[j];
        g_c = c;
    }
}

// ---------------- kernel 1: w[row] = x[row] . u + c ----------------
__global__ void w_kernel(const float* __restrict__ x) {
    int warp = threadIdx.x >> 5, lane = threadIdx.x & 31;
    int row = blockIdx.x * 8 + warp;
    const float* xr = x + (size_t)row * HH;
    float s = 0.f;
    #pragma unroll
    for (int m = 0; m < 8; m++) s += xr[m * 32 + lane] * g_u[m * 32 + lane];
    for (int o = 16; o; o >>= 1) s += __shfl_down_sync(0xffffffffu, s, o);
    if (!lane) g_w[row] = s + g_c;
}

// ---------------- kernel 2: Q/K GEMM (fp32, f32x2 packed FFMA) ----------------
// grid (128, 4): x tiles of 128 rows; y in {0,1}=q halves, {2,3}=k halves.
// Output written transposed [b][h][n]; q pre-scaled by 1/16.
__global__ __launch_bounds__(256, 1) void qk_kernel(
    const float* __restrict__ x, const float* __restrict__ Wq,
    const float* __restrict__ bq, const float* __restrict__ Wk,
    const float* __restrict__ bk) {
    __shared__ float xs[32 * 132];   // transposed x slice: xs[d][n]
    __shared__ float wsm[32 * 132];  // weight slice:      wsm[d][h]

    const int tid = threadIdx.x;
    const int hi = blockIdx.y;
    const float* W = (hi < 2) ? Wq : Wk;
    const float* bias = (hi < 2) ? bq : bk;
    float* outp = (hi < 2) ? g_q : g_k;
    const int h0 = (hi & 1) * 128;
    const float scale = (hi < 2) ? 0.0625f : 1.0f;
    const int n0 = blockIdx.x * 128;

    const int row0 = (tid >> 4) << 3;  // n micro-offset
    const int col0 = (tid & 15) << 3;  // h micro-offset

    unsigned long long acc[4][8];
    #pragma unroll
    for (int r = 0; r < 4; r++)
        #pragma unroll
        for (int c = 0; c < 8; c++) acc[r][c] = 0ULL;

    for (int kk = 0; kk < 8; kk++) {
        if (kk) __syncthreads();
        // stage x slice transposed
        #pragma unroll
        for (int i = 0; i < 4; i++) {
            int idx = tid + i * 256;
            int row = idx >> 3, f4 = idx & 7;
            float4 v = *(const float4*)(x + (size_t)(n0 + row) * HH + kk * 32 + f4 * 4);
            xs[(f4 * 4 + 0) * 132 + row] = v.x;
            xs[(f4 * 4 + 1) * 132 + row] = v.y;
            xs[(f4 * 4 + 2) * 132 + row] = v.z;
            xs[(f4 * 4 + 3) * 132 + row] = v.w;
        }
        // stage weight slice (already [d][h])
        #pragma unroll
        for (int i = 0; i < 4; i++) {
            int idx = tid + i * 256;
            int t = idx >> 5, c4 = idx & 31;
            *(float4*)(wsm + t * 132 + c4 * 4) =
                *(const float4*)(W + (size_t)(kk * 32 + t) * HH + h0 + c4 * 4);
        }
        __syncthreads();
        #pragma unroll 8
        for (int t = 0; t < 32; t++) {
            ulonglong2 A0 = *(const ulonglong2*)(xs + t * 132 + row0);
            ulonglong2 A1 = *(const ulonglong2*)(xs + t * 132 + row0 + 4);
            unsigned long long ap[4] = {A0.x, A0.y, A1.x, A1.y};
            const float* bp = wsm + t * 132 + col0;
            float4 b0 = *(const float4*)bp;
            float4 b1 = *(const float4*)(bp + 4);
            float bb[8] = {b0.x, b0.y, b0.z, b0.w, b1.x, b1.y, b1.z, b1.w};
            #pragma unroll
            for (int c = 0; c < 8; c++) {
                unsigned long long Bd = dup2(bb[c]);
                #pragma unroll
                for (int r = 0; r < 4; r++) acc[r][c] = ffma2(ap[r], Bd, acc[r][c]);
            }
        }
    }

    const int b = n0 >> 11;
    const int nloc = (n0 & 2047) + row0;
    #pragma unroll
    for (int c = 0; c < 8; c++) {
        int h = h0 + col0 + c;
        float bsv = bias[h];
        float2 p0 = unpk(acc[0][c]), p1 = unpk(acc[1][c]);
        float2 p2 = unpk(acc[2][c]), p3 = unpk(acc[3][c]);
        float4 lo = make_float4((p0.x + bsv) * scale, (p0.y + bsv) * scale,
                                (p1.x + bsv) * scale, (p1.y + bsv) * scale);
        float4 hv = make_float4((p2.x + bsv) * scale, (p2.y + bsv) * scale,
                                (p3.x + bsv) * scale, (p3.y + bsv) * scale);
        float* o = outp + ((size_t)(b * HH + h)) * NN + nloc;
        *(float4*)o = lo;
        *(float4*)(o + 4) = hv;
    }
}

// ---------------- kernel 3: fused attention ----------------
// grid (16, 8): q-tile of 128 rows per CTA, per batch. Streams all 2048 keys
// in 128-wide tiles; scores via f32x2 FFMA; softmax-weighted scalar reduction.
#define QS_F (256 * 132)
#define KSL_F (32 * 132)
#define SMEM_F (QS_F + 2 * KSL_F + 128 + 256)

__global__ __launch_bounds__(256, 1) void attn_kernel(const float* __restrict__ bw,
                                                      float* __restrict__ out) {
    extern __shared__ float sm[];
    float* qs = sm;                       // qs[h][n] full q tile (256 x 128)
    float* ks = sm + QS_F;                // double-buffered k slice (32 x 128)
    float* ws = sm + QS_F + 2 * KSL_F;    // key scalars w[m] for this tile
    float* snum = ws + 128;
    float* sden = snum + 128;

    const int tid = threadIdx.x;
    const int b = blockIdx.y;
    const int n0 = blockIdx.x * 128;
    const int row0 = (tid >> 4) << 3;  // q-row micro-offset
    const int col0 = (tid & 15) << 3;  // key micro-offset

    const unsigned qs_u = (unsigned)__cvta_generic_to_shared(qs);
    const unsigned ks_u = (unsigned)__cvta_generic_to_shared(ks);

    // async-stage the whole q tile (group 0)
    {
        const float* qsrc = g_q + (size_t)b * HH * NN + n0;
        #pragma unroll
        for (int i = 0; i < 32; i++) {
            int idx = tid + i * 256;
            int t = idx >> 5, ch = idx & 31;
            cp16(qs_u + (unsigned)(t * 132 + ch * 4) * 4, qsrc + (size_t)t * NN + ch * 4);
        }
        cp_commit();
    }

    float num[8], den[8];
    #pragma unroll
    for (int i = 0; i < 8; i++) { num[i] = 0.f; den[i] = 0.f; }

    const float* kbase = g_k + (size_t)b * HH * NN;

    for (int j = 0; j < 16; j++) {
        const int m0 = j * 128;
        if (j) __syncthreads();  // previous epilogue done (ws / buffers safe)
        if (tid < 128) ws[tid] = g_w[b * NN + m0 + tid];
        // slice 0 of this tile -> buf0
        #pragma unroll
        for (int i = 0; i < 4; i++) {
            int idx = tid + i * 256;
            int tl = idx >> 5, ch = idx & 31;
            cp16(ks_u + (unsigned)(tl * 132 + ch * 4) * 4,
                 kbase + (size_t)tl * NN + m0 + ch * 4);
        }
        cp_commit();

        unsigned long long sacc[4][8];
        #pragma unroll
        for (int r = 0; r < 4; r++)
            #pragma unroll
            for (int c = 0; c < 8; c++) sacc[r][c] = 0ULL;

        for (int s = 0; s < 8; s++) {
            if (s < 7) {  // prefetch next slice into the other buffer
                int nb = (s + 1) & 1;
                #pragma unroll
                for (int i = 0; i < 4; i++) {
                    int idx = tid + i * 256;
                    int tl = idx >> 5, ch = idx & 31;
                    cp16(ks_u + (unsigned)(nb * KSL_F + tl * 132 + ch * 4) * 4,
                         kbase + (size_t)((s + 1) * 32 + tl) * NN + m0 + ch * 4);
                }
                cp_commit();
                cp_wait<1>();
            } else {
                cp_wait<0>();
            }
            __syncthreads();
            const float* qb = qs + (s * 32) * 132;
            const float* kb = ks + (s & 1) * KSL_F;
            #pragma unroll 8
            for (int t = 0; t < 32; t++) {
                ulonglong2 A0 = *(const ulonglong2*)(qb + t * 132 + row0);
                ulonglong2 A1 = *(const ulonglong2*)(qb + t * 132 + row0 + 4);
                unsigned long long ap[4] = {A0.x, A0.y, A1.x, A1.y};
                const float* bp = kb + t * 132 + col0;
                float4 b0 = *(const float4*)bp;
                float4 b1 = *(const float4*)(bp + 4);
                float bb[8] = {b0.x, b0.y, b0.z, b0.w, b1.x, b1.y, b1.z, b1.w};
                #pragma unroll
                for (int c = 0; c < 8; c++) {
                    unsigned long long Bd = dup2(bb[c]);
                    #pragma unroll
                    for (int r = 0; r < 4; r++) sacc[r][c] = ffma2(ap[r], Bd, sacc[r][c]);
                }
            }
            __syncthreads();  // all threads done before this buffer is refilled
        }

        // epilogue: exp + weighted accumulation (scores already include 1/sqrt(H))
        #pragma unroll
        for (int c = 0; c < 8; c++) {
            float wv = ws[col0 + c];
            #pragma unroll
            for (int r = 0; r < 4; r++) {
                float2 p = unpk(sacc[r][c]);
                float e0 = __expf(p.x), e1 = __expf(p.y);
                num[2 * r] += e0 * wv;     den[2 * r] += e0;
                num[2 * r + 1] += e1 * wv; den[2 * r + 1] += e1;
            }
        }
    }

    // cross-thread reduction over the 16 column-groups
    __syncthreads();
    if (tid < 128) { snum[tid] = 0.f; sden[tid] = 0.f; }
    __syncthreads();
    #pragma unroll
    for (int i = 0; i < 8; i++) {
        atomicAdd(&snum[row0 + i], num[i]);
        atomicAdd(&sden[row0 + i], den[i]);
    }
    __syncthreads();
    if (tid < 128) {
        out[b * NN + n0 + tid] = snum[tid] / sden[tid] + bw[0];
    }
}

// ---------------- launch ----------------
extern "C" void kernel_launch(void* const* d_in, const int* in_sizes, int n_in,
                              void* d_out, int out_size) {
    const float* x  = (const float*)d_in[0];
    const float* Wq = (const float*)d_in[1];
    const float* bq = (const float*)d_in[2];
    const float* Wk = (const float*)d_in[3];
    const float* bk = (const float*)d_in[4];
    const float* Wv = (const float*)d_in[5];
    const float* bv = (const float*)d_in[6];
    const float* Ww = (const float*)d_in[7];
    const float* bw = (const float*)d_in[8];
    float* out = (float*)d_out;

    cudaFuncSetAttribute(attn_kernel, cudaFuncAttributeMaxDynamicSharedMemorySize,
                         SMEM_F * 4);

    prep_kernel<<<1, 256>>>(Wv, Ww, bv);
    w_kernel<<<BB * NN / 8, 256>>>(x);
    qk_kernel<<<dim3(128, 4), 256>>>(x, Wq, bq, Wk, bk);
    attn_kernel<<<dim3(16, 8), 256, SMEM_F * 4>>>(bw, out);
}

// round 4
// speedup vs baseline: 2.5744x; 2.5665x over previous
#include <cuda_runtime.h>
#include <cuda_bf16.h>
#include <cstdint>

#define BB 8
#define NN 2048
#define HH 256

// ---------------- device scratch ----------------
__device__ __align__(16) __nv_bfloat16 g_xh[BB*NN*HH];
__device__ __align__(16) __nv_bfloat16 g_xl[BB*NN*HH];
__device__ __align__(16) __nv_bfloat16 g_qh[BB*NN*HH];
__device__ __align__(16) __nv_bfloat16 g_ql[BB*NN*HH];
__device__ __align__(16) __nv_bfloat16 g_kh[BB*NN*HH];
__device__ __align__(16) __nv_bfloat16 g_kl[BB*NN*HH];
__device__ __align__(16) __nv_bfloat16 g_Wqh[HH*HH];
__device__ __align__(16) __nv_bfloat16 g_Wql[HH*HH];
__device__ __align__(16) __nv_bfloat16 g_Wkh[HH*HH];
__device__ __align__(16) __nv_bfloat16 g_Wkl[HH*HH];
__device__ __align__(16) float g_w[BB*NN];
__device__ __align__(16) float g_u[HH];
__device__ float g_c;

// ---------------- helpers ----------------
__device__ __forceinline__ uint32_t smem_u32(const void* p) {
    return (uint32_t)__cvta_generic_to_shared(p);
}
__device__ __forceinline__ void cp16(uint32_t dst, const void* src) {
    asm volatile("cp.async.cg.shared.global [%0], [%1], 16;" :: "r"(dst), "l"(src));
}
__device__ __forceinline__ void cp_commit() { asm volatile("cp.async.commit_group;"); }
template <int N> __device__ __forceinline__ void cp_wait() {
    asm volatile("cp.async.wait_group %0;" :: "n"(N) : "memory");
}
__device__ __forceinline__ void ldsm4(uint32_t* d, uint32_t addr) {
    asm volatile("ldmatrix.sync.aligned.m8n8.x4.shared.b16 {%0,%1,%2,%3}, [%4];"
        : "=r"(d[0]), "=r"(d[1]), "=r"(d[2]), "=r"(d[3]) : "r"(addr));
}
__device__ __forceinline__ void mma16816(float* c, const uint32_t* a,
                                         uint32_t b0, uint32_t b1) {
    asm volatile("mma.sync.aligned.m16n8k16.row.col.f32.bf16.bf16.f32 "
        "{%0,%1,%2,%3}, {%4,%5,%6,%7}, {%8,%9}, {%0,%1,%2,%3};"
        : "+f"(c[0]), "+f"(c[1]), "+f"(c[2]), "+f"(c[3])
        : "r"(a[0]), "r"(a[1]), "r"(a[2]), "r"(a[3]), "r"(b0), "r"(b1));
}
#define SW128(o) ((o) ^ (((o) >> 3) & 0x70))
__device__ __forceinline__ uint32_t pack_bf(__nv_bfloat16 a, __nv_bfloat16 b) {
    return (uint32_t)__bfloat16_as_ushort(a) | ((uint32_t)__bfloat16_as_ushort(b) << 16);
}
__device__ __forceinline__ void split2(float v, __nv_bfloat16& h, __nv_bfloat16& l) {
    h = __float2bfloat16(v);
    l = __float2bfloat16(v - __bfloat162float(h));
}

// Stage a 32-row x 256-dim bf16 hi/lo tile (SW128, 64-dim blocks). dst: hi, dst+16K: lo.
__device__ __forceinline__ void stage32(uint32_t dst, const __nv_bfloat16* ph,
                                        const __nv_bfloat16* pl, int tid) {
    #pragma unroll
    for (int i = 0; i < 4; i++) {
        int idx = tid + i * 256, r = idx >> 5, d = (idx & 31) * 8;
        uint32_t off = (uint32_t)(d >> 6) * 4096u + SW128((uint32_t)(r * 128 + (d & 63) * 2));
        cp16(dst + off, ph + (size_t)r * HH + d);
        cp16(dst + 16384u + off, pl + (size_t)r * HH + d);
    }
}
// Stage a 128-row A tile: hi at smb+0, lo at smb+65536.
__device__ __forceinline__ void stageA(uint32_t smb, const __nv_bfloat16* ph,
                                       const __nv_bfloat16* pl, int tid) {
    #pragma unroll
    for (int i = 0; i < 16; i++) {
        int idx = tid + i * 256, r = idx >> 5, d = (idx & 31) * 8;
        uint32_t off = (uint32_t)(d >> 6) * 16384u + SW128((uint32_t)(r * 128 + (d & 63) * 2));
        cp16(smb + off, ph + (size_t)r * HH + d);
        cp16(smb + 65536u + off, pl + (size_t)r * HH + d);
    }
}

// One 128x32x256 score block, 3-pass hi/lo. A at smb(+65536), B tile at kbuf(+16384).
__device__ __forceinline__ void score_iter(uint32_t smb, uint32_t kbuf, uint32_t sq,
                                           uint32_t sk0, uint32_t sk1, float a4[4][4]) {
    #pragma unroll
    for (int kk = 0; kk < 16; kk++) {
        const uint32_t cx = (uint32_t)(kk & 3) * 32u;
        const uint32_t bq = (uint32_t)(kk >> 2) * 16384u;
        const uint32_t bk = (uint32_t)(kk >> 2) * 4096u;
        uint32_t ah[4], al[4], b0h[4], b1h[4], b0l[4], b1l[4];
        ldsm4(ah, smb + bq + (sq ^ cx));
        ldsm4(al, smb + 65536u + bq + (sq ^ cx));
        ldsm4(b0h, kbuf + bk + (sk0 ^ cx));
        ldsm4(b1h, kbuf + bk + (sk1 ^ cx));
        ldsm4(b0l, kbuf + 16384u + bk + (sk0 ^ cx));
        ldsm4(b1l, kbuf + 16384u + bk + (sk1 ^ cx));
        mma16816(a4[0], ah, b0h[0], b0h[1]);
        mma16816(a4[1], ah, b0h[2], b0h[3]);
        mma16816(a4[2], ah, b1h[0], b1h[1]);
        mma16816(a4[3], ah, b1h[2], b1h[3]);
        mma16816(a4[0], ah, b0l[0], b0l[1]);
        mma16816(a4[1], ah, b0l[2], b0l[3]);
        mma16816(a4[2], ah, b1l[0], b1l[1]);
        mma16816(a4[3], ah, b1l[2], b1l[3]);
        mma16816(a4[0], al, b0h[0], b0h[1]);
        mma16816(a4[1], al, b0h[2], b0h[3]);
        mma16816(a4[2], al, b1h[0], b1h[1]);
        mma16816(a4[3], al, b1h[2], b1h[3]);
    }
}

// ---------------- kernel 0: u = Wv @ Ww, c = bv . Ww ----------------
__global__ void prep_kernel(const float* __restrict__ Wv, const float* __restrict__ Ww,
                            const float* __restrict__ bv) {
    int warp = threadIdx.x >> 5, lane = threadIdx.x & 31;
    for (int row = warp; row < HH; row += 8) {
        float s = 0.f;
        #pragma unroll
        for (int m = 0; m < 8; m++) s += Wv[row * HH + m * 32 + lane] * Ww[m * 32 + lane];
        for (int o = 16; o; o >>= 1) s += __shfl_down_sync(0xffffffffu, s, o);
        if (!lane) g_u[row] = s;
    }
    if (threadIdx.x == 0) {
        float c = 0.f;
        for (int j = 0; j < HH; j++) c += bv[j] * Ww[j];
        g_c = c;
    }
}

// ---------------- kernel 1: split x to bf16 hi/lo + w[row] = x.u + c ----------------
__global__ void xw_kernel(const float* __restrict__ x) {
    int warp = threadIdx.x >> 5, lane = threadIdx.x & 31;
    int row = blockIdx.x * 8 + warp;
    const float* xr = x + (size_t)row * HH + lane * 8;
    const float* up = g_u + lane * 8;
    uint32_t hi[4], lo[4];
    float s = 0.f;
    #pragma unroll
    for (int g = 0; g < 2; g++) {
        float4 v = *(const float4*)(xr + g * 4);
        __nv_bfloat16 h0, l0, h1, l1, h2, l2, h3, l3;
        split2(v.x, h0, l0); split2(v.y, h1, l1);
        split2(v.z, h2, l2); split2(v.w, h3, l3);
        hi[g * 2] = pack_bf(h0, h1); hi[g * 2 + 1] = pack_bf(h2, h3);
        lo[g * 2] = pack_bf(l0, l1); lo[g * 2 + 1] = pack_bf(l2, l3);
        s += v.x * up[g * 4] + v.y * up[g * 4 + 1] + v.z * up[g * 4 + 2] + v.w * up[g * 4 + 3];
    }
    *(uint4*)(g_xh + (size_t)row * HH + lane * 8) = *(uint4*)hi;
    *(uint4*)(g_xl + (size_t)row * HH + lane * 8) = *(uint4*)lo;
    for (int o = 16; o; o >>= 1) s += __shfl_down_sync(0xffffffffu, s, o);
    if (!lane) g_w[row] = s + g_c;
}

// ---------------- kernel 2: W^T bf16 hi/lo split ----------------
__global__ void prep_w_kernel(const float* __restrict__ Wq, const float* __restrict__ Wk) {
    int h = blockIdx.y, k = threadIdx.x;
    const float* W = blockIdx.x ? Wk : Wq;
    __nv_bfloat16* oh = blockIdx.x ? g_Wkh : g_Wqh;
    __nv_bfloat16* ol = blockIdx.x ? g_Wkl : g_Wql;
    __nv_bfloat16 hi, lo;
    split2(W[k * HH + h], hi, lo);
    oh[h * HH + k] = hi;
    ol[h * HH + k] = lo;
}

// ---------------- kernel 3: Q/K projection (mma.sync) ----------------
// grid (128, 2): 128-row x tiles; y: 0=q, 1=k. Full 256 output dims per CTA (8 n-iters).
// smem: A 131072 | B bufs 65536 | bias 1024
#define QK_SMEM 197632
__global__ __launch_bounds__(256, 1) void qk_mma2(const float* __restrict__ bq,
                                                  const float* __restrict__ bk) {
    extern __shared__ __align__(1024) char sm[];
    const uint32_t smb = smem_u32(sm);
    const int tid = threadIdx.x, warp = tid >> 5, lane = tid & 31;
    const bool isq = blockIdx.y == 0;
    const int m0 = blockIdx.x * 128;   // global x row

    stageA(smb, g_xh + (size_t)m0 * HH, g_xl + (size_t)m0 * HH, tid);
    if (tid < 64) cp16(smb + 196608u + tid * 16u, (isq ? bq : bk) + tid * 4);
    cp_commit();  // group 0
    const __nv_bfloat16* Wh = isq ? g_Wqh : g_Wkh;
    const __nv_bfloat16* Wl = isq ? g_Wql : g_Wkl;
    stage32(smb + 131072u, Wh, Wl, tid); cp_commit();               // group 1 (n 0-31)
    stage32(smb + 131072u + 32768u, Wh + 32 * HH, Wl + 32 * HH, tid); cp_commit();

    uint32_t qrowb = (uint32_t)((warp * 16 + (lane & 15)) * 128 + (lane >> 4) * 16);
    uint32_t sq = qrowb ^ ((qrowb >> 3) & 0x70);
    uint32_t kr0 = (uint32_t)((((lane & 7) + ((lane >> 4) << 3))) * 128 + ((lane & 8) << 1));
    uint32_t sk0 = kr0 ^ ((kr0 >> 3) & 0x70);
    uint32_t sk1 = sk0 + 2048u;

    const float scale = isq ? 0.0625f : 1.0f;
    __nv_bfloat16* oh = isq ? g_qh : g_kh;
    __nv_bfloat16* ol = isq ? g_ql : g_kl;
    const int r0 = m0 + warp * 16 + (lane >> 2);

    for (int j = 0; j < 8; j++) {
        cp_wait<1>(); __syncthreads();
        float acc[4][4];
        #pragma unroll
        for (int a = 0; a < 4; a++)
            #pragma unroll
            for (int b2 = 0; b2 < 4; b2++) acc[a][b2] = 0.f;
        score_iter(smb, smb + 131072u + (uint32_t)(j & 1) * 32768u, sq, sk0, sk1, acc);
        __syncthreads();
        if (j + 2 < 8) {
            stage32(smb + 131072u + (uint32_t)(j & 1) * 32768u,
                    Wh + (size_t)(j + 2) * 32 * HH, Wl + (size_t)(j + 2) * 32 * HH, tid);
            cp_commit();
        }
        const float* biasp = (const float*)(sm + 196608);
        #pragma unroll
        for (int nt = 0; nt < 4; nt++) {
            int col = j * 32 + nt * 8 + (lane & 3) * 2;
            float2 bi = *(const float2*)(biasp + col);
            float v00 = (acc[nt][0] + bi.x) * scale, v01 = (acc[nt][1] + bi.y) * scale;
            float v10 = (acc[nt][2] + bi.x) * scale, v11 = (acc[nt][3] + bi.y) * scale;
            __nv_bfloat16 h0, l0, h1, l1;
            split2(v00, h0, l0); split2(v01, h1, l1);
            *(uint32_t*)(oh + (size_t)r0 * HH + col) = pack_bf(h0, h1);
            *(uint32_t*)(ol + (size_t)r0 * HH + col) = pack_bf(l0, l1);
            split2(v10, h0, l0); split2(v11, h1, l1);
            *(uint32_t*)(oh + (size_t)(r0 + 8) * HH + col) = pack_bf(h0, h1);
            *(uint32_t*)(ol + (size_t)(r0 + 8) * HH + col) = pack_bf(l0, l1);
        }
    }
}

// ---------------- kernel 4: fused attention (mma.sync flash-style) ----------------
// grid (16, 8), 256 thr. smem: Q 131072 | K bufs 65536 | ws ring 512
#define AT_SMEM 197120
__global__ __launch_bounds__(256, 1) void attn_mma2(const float* __restrict__ bw,
                                                    float* __restrict__ out) {
    extern __shared__ __align__(1024) char sm[];
    const uint32_t smb = smem_u32(sm);
    const int tid = threadIdx.x, warp = tid >> 5, lane = tid & 31;
    const int b = blockIdx.y, n0 = blockIdx.x * 128;

    stageA(smb, g_qh + (size_t)(b * NN + n0) * HH, g_ql + (size_t)(b * NN + n0) * HH, tid);
    cp_commit();  // group 0
    const __nv_bfloat16* kh = g_kh + (size_t)b * NN * HH;
    const __nv_bfloat16* kl = g_kl + (size_t)b * NN * HH;
    const float* wsrc = g_w + b * NN;
    // tiles 0,1
    #pragma unroll
    for (int j0 = 0; j0 < 2; j0++) {
        stage32(smb + 131072u + (uint32_t)j0 * 32768u, kh + (size_t)j0 * 32 * HH,
                kl + (size_t)j0 * 32 * HH, tid);
        if (tid < 8) cp16(smb + 196608u + (uint32_t)j0 * 128u + tid * 16u,
                          wsrc + j0 * 32 + tid * 4);
        cp_commit();
    }

    uint32_t qrowb = (uint32_t)((warp * 16 + (lane & 15)) * 128 + (lane >> 4) * 16);
    uint32_t sq = qrowb ^ ((qrowb >> 3) & 0x70);
    uint32_t kr0 = (uint32_t)((((lane & 7) + ((lane >> 4) << 3))) * 128 + ((lane & 8) << 1));
    uint32_t sk0 = kr0 ^ ((kr0 >> 3) & 0x70);
    uint32_t sk1 = sk0 + 2048u;

    float num0 = 0.f, den0 = 0.f, num1 = 0.f, den1 = 0.f;
    for (int j = 0; j < 64; j++) {
        cp_wait<1>(); __syncthreads();
        float acc[4][4];
        #pragma unroll
        for (int a = 0; a < 4; a++)
            #pragma unroll
            for (int b2 = 0; b2 < 4; b2++) acc[a][b2] = 0.f;
        score_iter(smb, smb + 131072u + (uint32_t)(j & 1) * 32768u, sq, sk0, sk1, acc);
        __syncthreads();
        if (j + 2 < 64) {
            stage32(smb + 131072u + (uint32_t)(j & 1) * 32768u,
                    kh + (size_t)(j + 2) * 32 * HH, kl + (size_t)(j + 2) * 32 * HH, tid);
            if (tid < 8) cp16(smb + 196608u + (uint32_t)((j + 2) & 3) * 128u + tid * 16u,
                              wsrc + (j + 2) * 32 + tid * 4);
            cp_commit();
        }
        const float* wsp = (const float*)(sm + 196608 + (j & 3) * 128);
        #pragma unroll
        for (int nt = 0; nt < 4; nt++) {
            float2 wv = *(const float2*)(wsp + nt * 8 + (lane & 3) * 2);
            float e;
            e = __expf(acc[nt][0]); den0 += e; num0 += e * wv.x;
            e = __expf(acc[nt][1]); den0 += e; num0 += e * wv.y;
            e = __expf(acc[nt][2]); den1 += e; num1 += e * wv.x;
            e = __expf(acc[nt][3]); den1 += e; num1 += e * wv.y;
        }
    }
    #pragma unroll
    for (int o = 1; o <= 2; o <<= 1) {
        num0 += __shfl_xor_sync(0xffffffffu, num0, o);
        den0 += __shfl_xor_sync(0xffffffffu, den0, o);
        num1 += __shfl_xor_sync(0xffffffffu, num1, o);
        den1 += __shfl_xor_sync(0xffffffffu, den1, o);
    }
    if (!(lane & 3)) {
        int r = n0 + warp * 16 + (lane >> 2);
        float bwv = __ldg(bw);
        out[b * NN + r] = num0 / den0 + bwv;
        out[b * NN + r + 8] = num1 / den1 + bwv;
    }
}

// ---------------- launch ----------------
extern "C" void kernel_launch(void* const* d_in, const int* in_sizes, int n_in,
                              void* d_out, int out_size) {
    const float* x  = (const float*)d_in[0];
    const float* Wq = (const float*)d_in[1];
    const float* bq = (const float*)d_in[2];
    const float* Wk = (const float*)d_in[3];
    const float* bk = (const float*)d_in[4];
    const float* Wv = (const float*)d_in[5];
    const float* bv = (const float*)d_in[6];
    const float* Ww = (const float*)d_in[7];
    const float* bw = (const float*)d_in[8];
    float* out = (float*)d_out;

    cudaFuncSetAttribute(qk_mma2, cudaFuncAttributeMaxDynamicSharedMemorySize, QK_SMEM);
    cudaFuncSetAttribute(attn_mma2, cudaFuncAttributeMaxDynamicSharedMemorySize, AT_SMEM);

    prep_kernel<<<1, 256>>>(Wv, Ww, bv);
    xw_kernel<<<BB * NN / 8, 256>>>(x);
    prep_w_kernel<<<dim3(2, 256), 256>>>(Wq, Wk);
    qk_mma2<<<dim3(128, 2), 256, QK_SMEM>>>(bq, bk);
    attn_mma2<<<dim3(16, 8), 256, AT_SMEM>>>(bw, out);
}